// round 2
// baseline (speedup 1.0000x reference)
#include <cuda_runtime.h>
#include <cuda_bf16.h>
#include <math.h>

#define NN 8
#define CI 128
#define CO 128
#define HH 128
#define WW 128
#define HWSZ (HH*WW)
#define EPS 1e-5f

// Scratch (allocation-free requirement -> __device__ globals)
__device__ float g_y[NN*CO*HH*WW];      // conv output, 64 MB
__device__ float g_mean[NN*CO];
__device__ float g_rstd[NN*CO];

// ---------------- Conv 3x3 + bias ----------------
// Tile: 32x32 spatial, 16 output channels per block. 256 threads (32 x, 8 y).
// Each thread: 4 pixels (rows tyi, tyi+8, tyi+16, tyi+24 at column tx) x 16 channels.
#define TW 32
#define TH 32
#define BC 16
#define CONV_THREADS 256

__global__ __launch_bounds__(CONV_THREADS, 2)
void conv_bias_kernel(const float* __restrict__ x,
                      const float* __restrict__ w,
                      const float* __restrict__ bias)
{
    __shared__ float s_in[34*34];
    __shared__ float s_w[BC*9];

    const int n    = blockIdx.z;
    const int cg   = blockIdx.y;           // c_out group (0..7)
    const int tile = blockIdx.x;           // 0..15 (4x4 grid of 32x32 tiles)
    const int ty0  = (tile / (WW/TW)) * TH;
    const int tx0  = (tile % (WW/TW)) * TW;

    const int tx  = threadIdx.x & 31;      // 0..31 column within tile
    const int tyi = threadIdx.x >> 5;      // 0..7

    float acc[4][BC];
    #pragma unroll
    for (int p = 0; p < 4; p++)
        #pragma unroll
        for (int c = 0; c < BC; c++)
            acc[p][c] = 0.0f;

    const float* xn = x + (size_t)n * CI * HWSZ;

    for (int ci = 0; ci < CI; ci++) {
        // Cooperative load of 34x34 input tile (with zero halo)
        const float* xp = xn + (size_t)ci * HWSZ;
        for (int i = threadIdx.x; i < 34*34; i += CONV_THREADS) {
            int r  = i / 34;
            int c  = i - r * 34;
            int gy = ty0 - 1 + r;
            int gx = tx0 - 1 + c;
            float v = 0.0f;
            if (gy >= 0 && gy < HH && gx >= 0 && gx < WW)
                v = xp[gy * WW + gx];
            s_in[i] = v;
        }
        // Weights for this (c_out group, ci): 16*9 = 144 floats
        if (threadIdx.x < BC*9) {
            int c = threadIdx.x / 9;
            int k = threadIdx.x - c * 9;
            s_w[threadIdx.x] = w[((size_t)(cg*BC + c) * CI + ci) * 9 + k];
        }
        __syncthreads();

        // Load all 4 pixels' 3x3 windows into registers ONCE (36 regs),
        // then stream 16 channels x 9 weights over them. Cuts shared-load
        // traffic 4x vs. reloading weights per pixel.
        float in[4][9];
        #pragma unroll
        for (int p = 0; p < 4; p++) {
            const int r = tyi + p * 8;
            #pragma unroll
            for (int kh = 0; kh < 3; kh++)
                #pragma unroll
                for (int kw = 0; kw < 3; kw++)
                    in[p][kh*3+kw] = s_in[(r + kh) * 34 + tx + kw];
        }

        #pragma unroll
        for (int c = 0; c < BC; c++) {
            float wv[9];
            #pragma unroll
            for (int k = 0; k < 9; k++)
                wv[k] = s_w[c*9 + k];
            #pragma unroll
            for (int p = 0; p < 4; p++) {
                float a = acc[p][c];
                #pragma unroll
                for (int k = 0; k < 9; k++)
                    a = fmaf(in[p][k], wv[k], a);
                acc[p][c] = a;
            }
        }
        __syncthreads();
    }

    // Epilogue: add bias, store to scratch
    #pragma unroll
    for (int c = 0; c < BC; c++) {
        const int co = cg * BC + c;
        const float b = bias[co];
        float* yp = g_y + ((size_t)(n * CO + co)) * HWSZ;
        #pragma unroll
        for (int p = 0; p < 4; p++) {
            const int r = ty0 + tyi + p * 8;
            yp[r * WW + tx0 + tx] = acc[p][c] + b;
        }
    }
}

// ---------------- Per-instance stats ----------------
__global__ __launch_bounds__(256)
void stats_kernel()
{
    const int inst = blockIdx.x;           // n*CO + c, 0..1023
    const float* yp = g_y + (size_t)inst * HWSZ;

    float s = 0.0f, sq = 0.0f;
    for (int i = threadIdx.x; i < HWSZ / 4; i += 256) {
        float4 v = reinterpret_cast<const float4*>(yp)[i];
        s  += v.x + v.y + v.z + v.w;
        sq += v.x*v.x + v.y*v.y + v.z*v.z + v.w*v.w;
    }

    __shared__ float sh_s[32];
    __shared__ float sh_q[32];
    // warp reduce
    #pragma unroll
    for (int o = 16; o > 0; o >>= 1) {
        s  += __shfl_xor_sync(0xffffffffu, s,  o);
        sq += __shfl_xor_sync(0xffffffffu, sq, o);
    }
    const int wid = threadIdx.x >> 5;
    const int lid = threadIdx.x & 31;
    if (lid == 0) { sh_s[wid] = s; sh_q[wid] = sq; }
    __syncthreads();
    if (wid == 0) {
        s  = (lid < 8) ? sh_s[lid] : 0.0f;
        sq = (lid < 8) ? sh_q[lid] : 0.0f;
        #pragma unroll
        for (int o = 4; o > 0; o >>= 1) {
            s  += __shfl_xor_sync(0xffffffffu, s,  o);
            sq += __shfl_xor_sync(0xffffffffu, sq, o);
        }
        if (lid == 0) {
            const float mean = s * (1.0f / HWSZ);
            const float var  = sq * (1.0f / HWSZ) - mean * mean;
            g_mean[inst] = mean;
            g_rstd[inst] = rsqrtf(var + EPS);
        }
    }
}

// ---------------- Normalize + affine + ReLU ----------------
__global__ __launch_bounds__(256)
void norm_kernel(const float* __restrict__ gamma,
                 const float* __restrict__ beta,
                 float* __restrict__ out)
{
    const int i = blockIdx.x * blockDim.x + threadIdx.x;   // float4 index
    const int total4 = NN * CO * HWSZ / 4;
    if (i >= total4) return;

    const int inst = i / (HWSZ / 4);
    const int c    = inst & (CO - 1);
    const float m  = g_mean[inst];
    const float rs = g_rstd[inst];
    const float sc = rs * gamma[c];
    const float sh = beta[c] - m * sc;

    float4 v = reinterpret_cast<const float4*>(g_y)[i];
    float4 o;
    o.x = fmaxf(fmaf(v.x, sc, sh), 0.0f);
    o.y = fmaxf(fmaf(v.y, sc, sh), 0.0f);
    o.z = fmaxf(fmaf(v.z, sc, sh), 0.0f);
    o.w = fmaxf(fmaf(v.w, sc, sh), 0.0f);
    reinterpret_cast<float4*>(out)[i] = o;
}

extern "C" void kernel_launch(void* const* d_in, const int* in_sizes, int n_in,
                              void* d_out, int out_size)
{
    const float* x      = (const float*)d_in[0];
    const float* weight = (const float*)d_in[1];
    const float* bias   = (const float*)d_in[2];
    const float* gamma  = (const float*)d_in[3];
    const float* beta   = (const float*)d_in[4];
    float* out = (float*)d_out;

    dim3 cgrid(16, CO / BC, NN);           // 16 spatial tiles, 8 c-groups, 8 batch
    conv_bias_kernel<<<cgrid, CONV_THREADS>>>(x, weight, bias);

    stats_kernel<<<NN * CO, 256>>>();

    const int total4 = NN * CO * HWSZ / 4;
    norm_kernel<<<(total4 + 255) / 256, 256>>>(gamma, beta, out);
}

// round 4
// speedup vs baseline: 3.8621x; 3.8621x over previous
#include <cuda_runtime.h>
#include <cuda_bf16.h>
#include <math.h>
#include <stdint.h>

#define NN 8
#define CI 128
#define CO 128
#define HH 128
#define WW 128
#define HWSZ (HH*WW)
#define EPS 1e-5f

#define KC 64                  // ci per chunk
#define NCHUNK 2
#define NTAP 9
#define NSTAGE (NCHUNK*NTAP)   // 18
#define BROWS 3                // input rows (1 output row + halo)
#define BCOLS 130              // 128 + 2 halo
#define BPIX (BROWS*BCOLS)     // 390

// smem layout (bytes): A double buffer (hi 16K + lo 16K each), then B hi/lo
#define SMEM_ABUF   32768
#define SMEM_B_HI   65536
#define SMEM_B_SZ   50176      // 390*128 = 49920, padded to 1024
#define SMEM_B_LO   (SMEM_B_HI + SMEM_B_SZ)
#define SMEM_TOTAL  (SMEM_B_LO + SMEM_B_SZ)   // 165888

// scratch
__device__ float g_y[(size_t)NN*CO*HH*WW];
__device__ float g_sum[NN*CO];
__device__ float g_sq[NN*CO];
__device__ unsigned char g_wpack[NSTAGE*32768];  // [chunk*9+tap]: hi 16KB + lo 16KB, swizzled [co][ci]

// ---------------- helpers ----------------
__device__ __forceinline__ uint32_t smem_u32(const void* p) {
    uint32_t a;
    asm("{ .reg .u64 t; cvta.to.shared.u64 t, %1; cvt.u32.u64 %0, t; }" : "=r"(a) : "l"(p));
    return a;
}
__host__ __device__ __forceinline__ uint32_t swz128(uint32_t off) { return off ^ ((off >> 3) & 0x70); }

__device__ __forceinline__ void ldsm4(uint32_t* r, uint32_t addr) {
    asm volatile("ldmatrix.sync.aligned.m8n8.x4.shared.b16 {%0,%1,%2,%3}, [%4];"
                 : "=r"(r[0]), "=r"(r[1]), "=r"(r[2]), "=r"(r[3]) : "r"(addr));
}
__device__ __forceinline__ void mma16816(float* d, const uint32_t* a, uint32_t b0, uint32_t b1) {
    asm volatile("mma.sync.aligned.m16n8k16.row.col.f32.bf16.bf16.f32 "
                 "{%0,%1,%2,%3}, {%4,%5,%6,%7}, {%8,%9}, {%0,%1,%2,%3};"
                 : "+f"(d[0]), "+f"(d[1]), "+f"(d[2]), "+f"(d[3])
                 : "r"(a[0]), "r"(a[1]), "r"(a[2]), "r"(a[3]), "r"(b0), "r"(b1));
}
__device__ __forceinline__ void cp_async16(uint32_t dst, const void* src) {
    asm volatile("cp.async.cg.shared.global [%0], [%1], 16;" :: "r"(dst), "l"(src));
}
__device__ __forceinline__ void cp_commit()  { asm volatile("cp.async.commit_group;"); }
__device__ __forceinline__ void cp_waitall() { asm volatile("cp.async.wait_group 0;" ::: "memory"); }
__device__ __forceinline__ void sts16(uint32_t addr, unsigned short v) {
    asm volatile("st.shared.u16 [%0], %1;" :: "r"(addr), "h"(v));
}

// ---------------- zero sums ----------------
__global__ void zero_kernel() {
    int i = blockIdx.x * blockDim.x + threadIdx.x;
    if (i < NN*CO) { g_sum[i] = 0.0f; g_sq[i] = 0.0f; }
}

// ---------------- weight prepack: fp32 -> swizzled bf16 hi/lo images ----------------
__global__ void prepack_kernel(const float* __restrict__ w) {
    int idx = blockIdx.x * blockDim.x + threadIdx.x;   // (co*CI + ci)*9 + t
    if (idx >= CO*CI*NTAP) return;
    int t  = idx % 9;
    int ci = (idx / 9) % CI;
    int co = idx / (9*CI);
    float v = w[idx];
    __nv_bfloat16 hi = __float2bfloat16(v);
    __nv_bfloat16 lo = __float2bfloat16(v - __bfloat162float(hi));
    int chunk = ci >> 6, cil = ci & 63;
    int img = chunk*NTAP + t;
    uint32_t off = swz128((uint32_t)co*128 + (uint32_t)cil*2);
    *(__nv_bfloat16*)(g_wpack + (size_t)img*32768 + off)         = hi;
    *(__nv_bfloat16*)(g_wpack + (size_t)img*32768 + 16384 + off) = lo;
}

// ---------------- conv: implicit GEMM via mma.sync bf16 (3-pass hi/lo) ----------------
__global__ __launch_bounds__(256, 1)
void conv_mma_kernel(const float* __restrict__ x, const float* __restrict__ bias)
{
    extern __shared__ __align__(1024) unsigned char smem[];
    const uint32_t sbase = smem_u32(smem);
    const int tid    = threadIdx.x;
    const int lane   = tid & 31;
    const int w      = tid >> 5;
    const int warp_m = w >> 2;     // 0..1 : 64 co each
    const int warp_n = w & 3;      // 0..3 : 32 pixels each

    const int n  = blockIdx.x >> 7;    // image
    const int r0 = blockIdx.x & 127;   // output row

    const int mtx   = lane >> 3;       // ldmatrix matrix id this lane addresses
    const int rowin = lane & 7;

    // A ldmatrix per-thread constants (row = co, k-contiguous 128B rows, SW128)
    const uint32_t kca = (uint32_t)((mtx >> 1) * 16);
    uint32_t aoff[4], axr[4];
    #pragma unroll
    for (int mt = 0; mt < 4; mt++) {
        int co = warp_m*64 + mt*16 + (mtx & 1)*8 + rowin;
        aoff[mt] = (uint32_t)co * 128;
        axr[mt]  = (uint32_t)(co & 7) << 4;
    }
    const uint32_t kcb = (uint32_t)((mtx & 1) * 16);

    float acc[4][4][4];
    #pragma unroll
    for (int mt = 0; mt < 4; mt++)
        #pragma unroll
        for (int nt = 0; nt < 4; nt++)
            #pragma unroll
            for (int i = 0; i < 4; i++)
                acc[mt][nt][i] = 0.0f;

    // prologue: async-load A stage 0
    {
        const uint4* src = (const uint4*)g_wpack;
        #pragma unroll
        for (int j = 0; j < 8; j++)
            cp_async16(sbase + (uint32_t)(tid + j*256)*16, src + tid + j*256);
        cp_commit();
    }

    for (int s = 0; s < NSTAGE; s++) {
        const int chunk = s / NTAP;
        const int tap   = s - chunk*NTAP;

        if (tap == 0) {
            __syncthreads();   // all warps done reading previous chunk's B
            const int cb = chunk * KC;
            for (int u = w; u < BROWS*KC; u += 8) {
                const int rho = u >> 6;          // 0..2
                const int cil = u & 63;
                const int gr  = r0 - 1 + rho;
                const float* xp = x + (((size_t)n*CI + (cb + cil)) * HH + gr) * WW;
                const bool rok = (gr >= 0) & (gr < HH);
                #pragma unroll
                for (int c0 = 0; c0 < 160; c0 += 32) {
                    const int cc = c0 + lane;
                    if (cc < BCOLS) {
                        const int gc = cc - 1;
                        float v = (rok && gc >= 0 && gc < WW) ? __ldg(xp + gc) : 0.0f;
                        __nv_bfloat16 hi = __float2bfloat16(v);
                        __nv_bfloat16 lo = __float2bfloat16(v - __bfloat162float(hi));
                        const uint32_t off = swz128((uint32_t)(rho*BCOLS + cc)*128 + (uint32_t)cil*2);
                        sts16(sbase + SMEM_B_HI + off, *(unsigned short*)&hi);
                        sts16(sbase + SMEM_B_LO + off, *(unsigned short*)&lo);
                    }
                }
            }
        }

        cp_waitall();          // A[s] landed
        __syncthreads();       // A[s] + B visible; prior compute finished

        if (s + 1 < NSTAGE) {  // prefetch A[s+1] into the other buffer
            const uint4* src = (const uint4*)(g_wpack + (size_t)(s+1)*32768);
            const uint32_t dst = sbase + (uint32_t)((s+1) & 1) * SMEM_ABUF;
            #pragma unroll
            for (int j = 0; j < 8; j++)
                cp_async16(dst + (uint32_t)(tid + j*256)*16, src + tid + j*256);
            cp_commit();
        }

        // ---- compute stage s ----
        const uint32_t a_hi = sbase + (uint32_t)(s & 1) * SMEM_ABUF;
        const int kh = tap / 3, kw = tap - kh*3;
        uint32_t boff[2], bxr[2];
        #pragma unroll
        for (int p = 0; p < 2; p++) {
            int pix = kh*BCOLS + kw + warp_n*32 + p*16 + (mtx >> 1)*8 + rowin;
            boff[p] = (uint32_t)pix * 128;
            bxr[p]  = (uint32_t)(pix & 7) << 4;
        }

        #pragma unroll
        for (int ks = 0; ks < 4; ks++) {
            uint32_t ah[4][4], al[4][4];
            #pragma unroll
            for (int mt = 0; mt < 4; mt++) {
                const uint32_t ka = (uint32_t)ks*32 + kca;
                const uint32_t ad = a_hi + aoff[mt] + (ka ^ axr[mt]);
                ldsm4(ah[mt], ad);
                ldsm4(al[mt], ad + 16384);
            }
            uint32_t bh[2][4], bl[2][4];
            #pragma unroll
            for (int p = 0; p < 2; p++) {
                const uint32_t kb = (uint32_t)ks*32 + kcb;
                const uint32_t bd = sbase + SMEM_B_HI + boff[p] + (kb ^ bxr[p]);
                ldsm4(bh[p], bd);
                ldsm4(bl[p], bd + SMEM_B_SZ);
            }
            #pragma unroll
            for (int mt = 0; mt < 4; mt++)
                #pragma unroll
                for (int nt = 0; nt < 4; nt++) {
                    const int p = nt >> 1, q = (nt & 1) * 2;
                    mma16816(acc[mt][nt], ah[mt], bh[p][q], bh[p][q+1]);  // hi*hi
                    mma16816(acc[mt][nt], al[mt], bh[p][q], bh[p][q+1]);  // lo(W)*hi(X)
                    mma16816(acc[mt][nt], ah[mt], bl[p][q], bl[p][q+1]);  // hi(W)*lo(X)
                }
        }
    }

    // ---- epilogue: bias + store + instance sums ----
    const int g  = lane >> 2;
    const int tg = lane & 3;
    #pragma unroll
    for (int mt = 0; mt < 4; mt++) {
        const int co0 = warp_m*64 + mt*16 + g;
        const int co1 = co0 + 8;
        const float b0 = __ldg(bias + co0);
        const float b1 = __ldg(bias + co1);
        float* yp0 = g_y + ((size_t)(n*CO + co0) * HH + r0) * WW;
        float* yp1 = g_y + ((size_t)(n*CO + co1) * HH + r0) * WW;
        float s0 = 0.f, q0 = 0.f, s1 = 0.f, q1 = 0.f;
        #pragma unroll
        for (int nt = 0; nt < 4; nt++) {
            const int pix = warp_n*32 + nt*8 + 2*tg;
            float v0 = acc[mt][nt][0] + b0;
            float v1 = acc[mt][nt][1] + b0;
            float v2 = acc[mt][nt][2] + b1;
            float v3 = acc[mt][nt][3] + b1;
            float2 o0 = {v0, v1}, o1 = {v2, v3};
            *(float2*)(yp0 + pix) = o0;
            *(float2*)(yp1 + pix) = o1;
            s0 += v0 + v1;  q0 += v0*v0 + v1*v1;
            s1 += v2 + v3;  q1 += v2*v2 + v3*v3;
        }
        #pragma unroll
        for (int o = 1; o <= 2; o <<= 1) {
            s0 += __shfl_xor_sync(0xffffffffu, s0, o);
            q0 += __shfl_xor_sync(0xffffffffu, q0, o);
            s1 += __shfl_xor_sync(0xffffffffu, s1, o);
            q1 += __shfl_xor_sync(0xffffffffu, q1, o);
        }
        if (tg == 0) {
            atomicAdd(&g_sum[n*CO + co0], s0);
            atomicAdd(&g_sq [n*CO + co0], q0);
            atomicAdd(&g_sum[n*CO + co1], s1);
            atomicAdd(&g_sq [n*CO + co1], q1);
        }
    }
}

// ---------------- normalize + affine + ReLU ----------------
__global__ __launch_bounds__(256)
void norm_kernel(const float* __restrict__ gamma, const float* __restrict__ beta,
                 float* __restrict__ out)
{
    const int inst = blockIdx.x;
    const int c = inst & (CO - 1);
    const float mean = g_sum[inst] * (1.0f / HWSZ);
    const float var  = g_sq[inst] * (1.0f / HWSZ) - mean * mean;
    const float rstd = rsqrtf(var + EPS);
    const float sc = rstd * gamma[c];
    const float sh = beta[c] - mean * sc;

    const float4* yp = (const float4*)(g_y + (size_t)inst * HWSZ);
    float4* op = (float4*)(out + (size_t)inst * HWSZ);
    for (int i = threadIdx.x; i < HWSZ/4; i += 256) {
        float4 v = yp[i];
        float4 o;
        o.x = fmaxf(fmaf(v.x, sc, sh), 0.0f);
        o.y = fmaxf(fmaf(v.y, sc, sh), 0.0f);
        o.z = fmaxf(fmaf(v.z, sc, sh), 0.0f);
        o.w = fmaxf(fmaf(v.w, sc, sh), 0.0f);
        op[i] = o;
    }
}

extern "C" void kernel_launch(void* const* d_in, const int* in_sizes, int n_in,
                              void* d_out, int out_size)
{
    const float* x      = (const float*)d_in[0];
    const float* weight = (const float*)d_in[1];
    const float* bias   = (const float*)d_in[2];
    const float* gamma  = (const float*)d_in[3];
    const float* beta   = (const float*)d_in[4];
    float* out = (float*)d_out;

    cudaFuncSetAttribute(conv_mma_kernel, cudaFuncAttributeMaxDynamicSharedMemorySize, SMEM_TOTAL);

    zero_kernel<<<(NN*CO + 255)/256, 256>>>();
    prepack_kernel<<<(CO*CI*NTAP + 255)/256, 256>>>(weight);
    conv_mma_kernel<<<NN*HH, 256, SMEM_TOTAL>>>(x, bias);
    norm_kernel<<<NN*CO, 256>>>(gamma, beta, out);
}

// round 6
// speedup vs baseline: 4.4249x; 1.1457x over previous
#include <cuda_runtime.h>
#include <cuda_bf16.h>
#include <math.h>
#include <stdint.h>

#define NN 8
#define CI 128
#define CO 128
#define HH 128
#define WW 128
#define HWSZ (HH*WW)
#define EPS 1e-5f

#define KC 64                  // ci per chunk
#define NCHUNK 2
#define NTAP 9
#define NSTAGE (NCHUNK*NTAP)   // 18
#define BROWS 3                // input rows (1 output row + halo)
#define BCOLS 130              // 128 + 2 halo
#define BPIX (BROWS*BCOLS)     // 390

#define CONV_THREADS 512       // 16 warps -> 4 per SMSP for latency hiding

// smem layout (bytes): A double buffer (hi 16K + lo 16K each), then B hi/lo
#define SMEM_ABUF   32768
#define SMEM_B_HI   65536
#define SMEM_B_SZ   50176      // 390*128 = 49920, padded to 1024
#define SMEM_B_LO   (SMEM_B_HI + SMEM_B_SZ)
#define SMEM_TOTAL  (SMEM_B_LO + SMEM_B_SZ)   // 165888

// scratch
__device__ float g_y[(size_t)NN*CO*HH*WW];
__device__ float g_sum[NN*CO];
__device__ float g_sq[NN*CO];
__device__ unsigned char g_wpack[NSTAGE*32768];  // [chunk*9+tap]: hi 16KB + lo 16KB, swizzled [co][ci]

// ---------------- helpers ----------------
__device__ __forceinline__ uint32_t smem_u32(const void* p) {
    uint32_t a;
    asm("{ .reg .u64 t; cvta.to.shared.u64 t, %1; cvt.u32.u64 %0, t; }" : "=r"(a) : "l"(p));
    return a;
}
__host__ __device__ __forceinline__ uint32_t swz128(uint32_t off) { return off ^ ((off >> 3) & 0x70); }

__device__ __forceinline__ void ldsm4(uint32_t* r, uint32_t addr) {
    asm volatile("ldmatrix.sync.aligned.m8n8.x4.shared.b16 {%0,%1,%2,%3}, [%4];"
                 : "=r"(r[0]), "=r"(r[1]), "=r"(r[2]), "=r"(r[3]) : "r"(addr));
}
__device__ __forceinline__ void mma16816(float* d, const uint32_t* a, uint32_t b0, uint32_t b1) {
    asm volatile("mma.sync.aligned.m16n8k16.row.col.f32.bf16.bf16.f32 "
                 "{%0,%1,%2,%3}, {%4,%5,%6,%7}, {%8,%9}, {%0,%1,%2,%3};"
                 : "+f"(d[0]), "+f"(d[1]), "+f"(d[2]), "+f"(d[3])
                 : "r"(a[0]), "r"(a[1]), "r"(a[2]), "r"(a[3]), "r"(b0), "r"(b1));
}
__device__ __forceinline__ void cp_async16(uint32_t dst, const void* src) {
    asm volatile("cp.async.cg.shared.global [%0], [%1], 16;" :: "r"(dst), "l"(src));
}
__device__ __forceinline__ void cp_commit()  { asm volatile("cp.async.commit_group;"); }
__device__ __forceinline__ void cp_waitall() { asm volatile("cp.async.wait_group 0;" ::: "memory"); }
__device__ __forceinline__ void sts16(uint32_t addr, unsigned short v) {
    asm volatile("st.shared.u16 [%0], %1;" :: "r"(addr), "h"(v));
}

// ---------------- zero sums ----------------
__global__ void zero_kernel() {
    int i = blockIdx.x * blockDim.x + threadIdx.x;
    if (i < NN*CO) { g_sum[i] = 0.0f; g_sq[i] = 0.0f; }
}

// ---------------- weight prepack: fp32 -> swizzled bf16 hi/lo images ----------------
__global__ void prepack_kernel(const float* __restrict__ w) {
    int idx = blockIdx.x * blockDim.x + threadIdx.x;   // (co*CI + ci)*9 + t
    if (idx >= CO*CI*NTAP) return;
    int t  = idx % 9;
    int ci = (idx / 9) % CI;
    int co = idx / (9*CI);
    float v = w[idx];
    __nv_bfloat16 hi = __float2bfloat16(v);
    __nv_bfloat16 lo = __float2bfloat16(v - __bfloat162float(hi));
    int chunk = ci >> 6, cil = ci & 63;
    int img = chunk*NTAP + t;
    uint32_t off = swz128((uint32_t)co*128 + (uint32_t)cil*2);
    *(__nv_bfloat16*)(g_wpack + (size_t)img*32768 + off)         = hi;
    *(__nv_bfloat16*)(g_wpack + (size_t)img*32768 + 16384 + off) = lo;
}

// ---------------- conv: implicit GEMM via mma.sync bf16 (3-pass hi/lo) ----------------
// 512 threads = 16 warps. Warp tile: 32 co x 32 pixels (2 x 4 mma tiles).
__global__ __launch_bounds__(CONV_THREADS, 1)
void conv_mma_kernel(const float* __restrict__ x, const float* __restrict__ bias)
{
    extern __shared__ __align__(1024) unsigned char smem[];
    const uint32_t sbase = smem_u32(smem);
    const int tid    = threadIdx.x;
    const int lane   = tid & 31;
    const int w      = tid >> 5;       // 0..15
    const int warp_m = w >> 2;         // 0..3 : 32 co each
    const int warp_n = w & 3;          // 0..3 : 32 pixels each

    const int n  = blockIdx.x >> 7;    // image
    const int r0 = blockIdx.x & 127;   // output row

    const int mtx   = lane >> 3;       // ldmatrix matrix id this lane addresses
    const int rowin = lane & 7;

    // A ldmatrix per-thread constants (row = co, k-contiguous 128B rows, SW128)
    const uint32_t kca = (uint32_t)((mtx >> 1) * 16);
    uint32_t aoff[2], axr[2];
    #pragma unroll
    for (int mt = 0; mt < 2; mt++) {
        int co = warp_m*32 + mt*16 + (mtx & 1)*8 + rowin;
        aoff[mt] = (uint32_t)co * 128;
        axr[mt]  = (uint32_t)(co & 7) << 4;
    }
    const uint32_t kcb = (uint32_t)((mtx & 1) * 16);

    float acc[2][4][4];
    #pragma unroll
    for (int mt = 0; mt < 2; mt++)
        #pragma unroll
        for (int nt = 0; nt < 4; nt++)
            #pragma unroll
            for (int i = 0; i < 4; i++)
                acc[mt][nt][i] = 0.0f;

    // prologue: async-load A stage 0 (32KB = 2048 uint4, 512 threads x 4)
    {
        const uint4* src = (const uint4*)g_wpack;
        #pragma unroll
        for (int j = 0; j < 4; j++)
            cp_async16(sbase + (uint32_t)(tid + j*CONV_THREADS)*16, src + tid + j*CONV_THREADS);
        cp_commit();
    }

    for (int s = 0; s < NSTAGE; s++) {
        const int chunk = s / NTAP;
        const int tap   = s - chunk*NTAP;

        if (tap == 0) {
            __syncthreads();   // all warps done reading previous chunk's B
            const int cb = chunk * KC;
            for (int u = w; u < BROWS*KC; u += 16) {
                const int rho = u >> 6;          // 0..2
                const int cil = u & 63;
                const int gr  = r0 - 1 + rho;
                const float* xp = x + (((size_t)n*CI + (cb + cil)) * HH + gr) * WW;
                const bool rok = (gr >= 0) & (gr < HH);
                #pragma unroll
                for (int c0 = 0; c0 < 160; c0 += 32) {
                    const int cc = c0 + lane;
                    if (cc < BCOLS) {
                        const int gc = cc - 1;
                        float v = (rok && gc >= 0 && gc < WW) ? __ldg(xp + gc) : 0.0f;
                        __nv_bfloat16 hi = __float2bfloat16(v);
                        __nv_bfloat16 lo = __float2bfloat16(v - __bfloat162float(hi));
                        const uint32_t off = swz128((uint32_t)(rho*BCOLS + cc)*128 + (uint32_t)cil*2);
                        sts16(sbase + SMEM_B_HI + off, *(unsigned short*)&hi);
                        sts16(sbase + SMEM_B_LO + off, *(unsigned short*)&lo);
                    }
                }
            }
        }

        cp_waitall();          // A[s] landed
        __syncthreads();       // A[s] + B visible; prior compute finished

        if (s + 1 < NSTAGE) {  // prefetch A[s+1] into the other buffer
            const uint4* src = (const uint4*)(g_wpack + (size_t)(s+1)*32768);
            const uint32_t dst = sbase + (uint32_t)((s+1) & 1) * SMEM_ABUF;
            #pragma unroll
            for (int j = 0; j < 4; j++)
                cp_async16(dst + (uint32_t)(tid + j*CONV_THREADS)*16, src + tid + j*CONV_THREADS);
            cp_commit();
        }

        // ---- compute stage s ----
        const uint32_t a_hi = sbase + (uint32_t)(s & 1) * SMEM_ABUF;
        const int kh = tap / 3, kw = tap - kh*3;
        uint32_t boff[2], bxr[2];
        #pragma unroll
        for (int p = 0; p < 2; p++) {
            int pix = kh*BCOLS + kw + warp_n*32 + p*16 + (mtx >> 1)*8 + rowin;
            boff[p] = (uint32_t)pix * 128;
            bxr[p]  = (uint32_t)(pix & 7) << 4;
        }

        #pragma unroll
        for (int ks = 0; ks < 4; ks++) {
            uint32_t ah[2][4], al[2][4];
            #pragma unroll
            for (int mt = 0; mt < 2; mt++) {
                const uint32_t ka = (uint32_t)ks*32 + kca;
                const uint32_t ad = a_hi + aoff[mt] + (ka ^ axr[mt]);
                ldsm4(ah[mt], ad);
                ldsm4(al[mt], ad + 16384);
            }
            uint32_t bh[2][4], bl[2][4];
            #pragma unroll
            for (int p = 0; p < 2; p++) {
                const uint32_t kb = (uint32_t)ks*32 + kcb;
                const uint32_t bd = sbase + SMEM_B_HI + boff[p] + (kb ^ bxr[p]);
                ldsm4(bh[p], bd);
                ldsm4(bl[p], bd + SMEM_B_SZ);
            }
            #pragma unroll
            for (int mt = 0; mt < 2; mt++)
                #pragma unroll
                for (int nt = 0; nt < 4; nt++) {
                    const int p = nt >> 1, q = (nt & 1) * 2;
                    mma16816(acc[mt][nt], ah[mt], bh[p][q], bh[p][q+1]);  // hi*hi
                    mma16816(acc[mt][nt], al[mt], bh[p][q], bh[p][q+1]);  // lo(W)*hi(X)
                    mma16816(acc[mt][nt], ah[mt], bl[p][q], bl[p][q+1]);  // hi(W)*lo(X)
                }
        }
    }

    // ---- epilogue: bias + store + instance sums ----
    const int g  = lane >> 2;
    const int tg = lane & 3;
    #pragma unroll
    for (int mt = 0; mt < 2; mt++) {
        const int co0 = warp_m*32 + mt*16 + g;
        const int co1 = co0 + 8;
        const float b0 = __ldg(bias + co0);
        const float b1 = __ldg(bias + co1);
        float* yp0 = g_y + ((size_t)(n*CO + co0) * HH + r0) * WW;
        float* yp1 = g_y + ((size_t)(n*CO + co1) * HH + r0) * WW;
        float s0 = 0.f, q0 = 0.f, s1 = 0.f, q1 = 0.f;
        #pragma unroll
        for (int nt = 0; nt < 4; nt++) {
            const int pix = warp_n*32 + nt*8 + 2*tg;
            float v0 = acc[mt][nt][0] + b0;
            float v1 = acc[mt][nt][1] + b0;
            float v2 = acc[mt][nt][2] + b1;
            float v3 = acc[mt][nt][3] + b1;
            float2 o0 = {v0, v1}, o1 = {v2, v3};
            *(float2*)(yp0 + pix) = o0;
            *(float2*)(yp1 + pix) = o1;
            s0 += v0 + v1;  q0 += v0*v0 + v1*v1;
            s1 += v2 + v3;  q1 += v2*v2 + v3*v3;
        }
        #pragma unroll
        for (int o = 1; o <= 2; o <<= 1) {
            s0 += __shfl_xor_sync(0xffffffffu, s0, o);
            q0 += __shfl_xor_sync(0xffffffffu, q0, o);
            s1 += __shfl_xor_sync(0xffffffffu, s1, o);
            q1 += __shfl_xor_sync(0xffffffffu, q1, o);
        }
        if (tg == 0) {
            atomicAdd(&g_sum[n*CO + co0], s0);
            atomicAdd(&g_sq [n*CO + co0], q0);
            atomicAdd(&g_sum[n*CO + co1], s1);
            atomicAdd(&g_sq [n*CO + co1], q1);
        }
    }
}

// ---------------- normalize + affine + ReLU ----------------
__global__ __launch_bounds__(256)
void norm_kernel(const float* __restrict__ gamma, const float* __restrict__ beta,
                 float* __restrict__ out)
{
    const int inst = blockIdx.x;
    const int c = inst & (CO - 1);
    const float mean = g_sum[inst] * (1.0f / HWSZ);
    const float var  = g_sq[inst] * (1.0f / HWSZ) - mean * mean;
    const float rstd = rsqrtf(var + EPS);
    const float sc = rstd * gamma[c];
    const float sh = beta[c] - mean * sc;

    const float4* yp = (const float4*)(g_y + (size_t)inst * HWSZ);
    float4* op = (float4*)(out + (size_t)inst * HWSZ);
    for (int i = threadIdx.x; i < HWSZ/4; i += 256) {
        float4 v = yp[i];
        float4 o;
        o.x = fmaxf(fmaf(v.x, sc, sh), 0.0f);
        o.y = fmaxf(fmaf(v.y, sc, sh), 0.0f);
        o.z = fmaxf(fmaf(v.z, sc, sh), 0.0f);
        o.w = fmaxf(fmaf(v.w, sc, sh), 0.0f);
        op[i] = o;
    }
}

extern "C" void kernel_launch(void* const* d_in, const int* in_sizes, int n_in,
                              void* d_out, int out_size)
{
    const float* x      = (const float*)d_in[0];
    const float* weight = (const float*)d_in[1];
    const float* bias   = (const float*)d_in[2];
    const float* gamma  = (const float*)d_in[3];
    const float* beta   = (const float*)d_in[4];
    float* out = (float*)d_out;

    cudaFuncSetAttribute(conv_mma_kernel, cudaFuncAttributeMaxDynamicSharedMemorySize, SMEM_TOTAL);

    zero_kernel<<<(NN*CO + 255)/256, 256>>>();
    prepack_kernel<<<(CO*CI*NTAP + 255)/256, 256>>>(weight);
    conv_mma_kernel<<<NN*HH, CONV_THREADS, SMEM_TOTAL>>>(x, bias);
    norm_kernel<<<NN*CO, 256>>>(gamma, beta, out);
}

// round 7
// speedup vs baseline: 4.5902x; 1.0374x over previous
#include <cuda_runtime.h>
#include <cuda_bf16.h>
#include <math.h>
#include <stdint.h>

#define NN 8
#define CI 128
#define CO 128
#define HH 128
#define WW 128
#define HWSZ (HH*WW)
#define EPS 1e-5f

#define KC 64                  // ci per chunk
#define NCHUNK 2
#define NTAP 9
#define NSTAGE (NCHUNK*NTAP)   // 18
#define ROWS_PER_CTA 2
#define BROWS 4                // input rows (2 output rows + halo)
#define BCOLS 130              // 128 + 2 halo
#define BPIX (BROWS*BCOLS)     // 520

#define CONV_THREADS 512       // 16 warps

// smem layout (bytes): A double buffer (hi 16K + lo 16K each), then B hi/lo
#define SMEM_ABUF   32768
#define SMEM_B_HI   65536
#define SMEM_B_SZ   (BPIX*128)            // 66560
#define SMEM_B_LO   (SMEM_B_HI + SMEM_B_SZ)
#define SMEM_TOTAL  (SMEM_B_LO + SMEM_B_SZ)   // 198656

// scratch
__device__ float g_y[(size_t)NN*CO*HH*WW];
__device__ float g_sum[NN*CO];
__device__ float g_sq[NN*CO];
__device__ unsigned char g_wpack[NSTAGE*32768];  // [chunk*9+tap]: hi 16KB + lo 16KB, swizzled [co][ci]

// ---------------- helpers ----------------
__device__ __forceinline__ uint32_t smem_u32(const void* p) {
    uint32_t a;
    asm("{ .reg .u64 t; cvta.to.shared.u64 t, %1; cvt.u32.u64 %0, t; }" : "=r"(a) : "l"(p));
    return a;
}
__host__ __device__ __forceinline__ uint32_t swz128(uint32_t off) { return off ^ ((off >> 3) & 0x70); }

__device__ __forceinline__ void ldsm4(uint32_t* r, uint32_t addr) {
    asm volatile("ldmatrix.sync.aligned.m8n8.x4.shared.b16 {%0,%1,%2,%3}, [%4];"
                 : "=r"(r[0]), "=r"(r[1]), "=r"(r[2]), "=r"(r[3]) : "r"(addr));
}
__device__ __forceinline__ void mma16816(float* d, const uint32_t* a, uint32_t b0, uint32_t b1) {
    asm volatile("mma.sync.aligned.m16n8k16.row.col.f32.bf16.bf16.f32 "
                 "{%0,%1,%2,%3}, {%4,%5,%6,%7}, {%8,%9}, {%0,%1,%2,%3};"
                 : "+f"(d[0]), "+f"(d[1]), "+f"(d[2]), "+f"(d[3])
                 : "r"(a[0]), "r"(a[1]), "r"(a[2]), "r"(a[3]), "r"(b0), "r"(b1));
}
__device__ __forceinline__ void cp_async16(uint32_t dst, const void* src) {
    asm volatile("cp.async.cg.shared.global [%0], [%1], 16;" :: "r"(dst), "l"(src));
}
__device__ __forceinline__ void cp_commit()  { asm volatile("cp.async.commit_group;"); }
__device__ __forceinline__ void cp_waitall() { asm volatile("cp.async.wait_group 0;" ::: "memory"); }
__device__ __forceinline__ void sts16(uint32_t addr, unsigned short v) {
    asm volatile("st.shared.u16 [%0], %1;" :: "r"(addr), "h"(v));
}

// ---------------- weight prepack (+ zero sums folded in) ----------------
__global__ void prepack_kernel(const float* __restrict__ w) {
    int idx = blockIdx.x * blockDim.x + threadIdx.x;   // (co*CI + ci)*9 + t
    if (idx < NN*CO) { g_sum[idx] = 0.0f; g_sq[idx] = 0.0f; }
    if (idx >= CO*CI*NTAP) return;
    int t  = idx % 9;
    int ci = (idx / 9) % CI;
    int co = idx / (9*CI);
    float v = w[idx];
    __nv_bfloat16 hi = __float2bfloat16(v);
    __nv_bfloat16 lo = __float2bfloat16(v - __bfloat162float(hi));
    int chunk = ci >> 6, cil = ci & 63;
    int img = chunk*NTAP + t;
    uint32_t off = swz128((uint32_t)co*128 + (uint32_t)cil*2);
    *(__nv_bfloat16*)(g_wpack + (size_t)img*32768 + off)         = hi;
    *(__nv_bfloat16*)(g_wpack + (size_t)img*32768 + 16384 + off) = lo;
}

// ---------------- conv: implicit GEMM via mma.sync bf16 (3-pass hi/lo) ----------------
// 512 threads = 16 warps. CTA: 128 co x 256 pixels (2 output rows).
// Warp tile: 32 co x 64 pixels (2 x 8 mma tiles).
__global__ __launch_bounds__(CONV_THREADS, 1)
void conv_mma_kernel(const float* __restrict__ x, const float* __restrict__ bias)
{
    extern __shared__ __align__(1024) unsigned char smem[];
    const uint32_t sbase = smem_u32(smem);
    const int tid    = threadIdx.x;
    const int lane   = tid & 31;
    const int w      = tid >> 5;       // 0..15
    const int warp_m = w >> 2;         // 0..3 : 32 co each
    const int warp_n = w & 3;          // 0..3 : 64 pixels each
    const int hrow   = warp_n >> 1;    // output row within CTA (0/1)
    const int colb   = (warp_n & 1) * 64;

    const int n  = blockIdx.x >> 6;             // image
    const int r0 = (blockIdx.x & 63) * ROWS_PER_CTA;

    const int mtx   = lane >> 3;       // ldmatrix matrix id this lane addresses
    const int rowin = lane & 7;

    // A ldmatrix per-thread constants (row = co, k-contiguous 128B rows, SW128)
    const uint32_t kca = (uint32_t)((mtx >> 1) * 16);
    uint32_t aoff[2], axr[2];
    #pragma unroll
    for (int mt = 0; mt < 2; mt++) {
        int co = warp_m*32 + mt*16 + (mtx & 1)*8 + rowin;
        aoff[mt] = (uint32_t)co * 128;
        axr[mt]  = (uint32_t)(co & 7) << 4;
    }
    const uint32_t kcb = (uint32_t)((mtx & 1) * 16);

    float acc[2][8][4];
    #pragma unroll
    for (int mt = 0; mt < 2; mt++)
        #pragma unroll
        for (int nt = 0; nt < 8; nt++)
            #pragma unroll
            for (int i = 0; i < 4; i++)
                acc[mt][nt][i] = 0.0f;

    // prologue: async-load A stage 0 (32KB = 2048 uint4, 512 threads x 4)
    {
        const uint4* src = (const uint4*)g_wpack;
        #pragma unroll
        for (int j = 0; j < 4; j++)
            cp_async16(sbase + (uint32_t)(tid + j*CONV_THREADS)*16, src + tid + j*CONV_THREADS);
        cp_commit();
    }

    for (int s = 0; s < NSTAGE; s++) {
        const int chunk = s / NTAP;
        const int tap   = s - chunk*NTAP;

        if (tap == 0) {
            __syncthreads();   // all warps done reading previous chunk's B
            const int cb = chunk * KC;
            for (int u = w; u < BROWS*KC; u += 16) {
                const int rho = u >> 6;          // 0..3
                const int cil = u & 63;
                const int gr  = r0 - 1 + rho;
                const float* xp = x + (((size_t)n*CI + (cb + cil)) * HH + gr) * WW;
                const bool rok = (gr >= 0) & (gr < HH);
                #pragma unroll
                for (int c0 = 0; c0 < 160; c0 += 32) {
                    const int cc = c0 + lane;
                    if (cc < BCOLS) {
                        const int gc = cc - 1;
                        float v = (rok && gc >= 0 && gc < WW) ? __ldg(xp + gc) : 0.0f;
                        __nv_bfloat16 hi = __float2bfloat16(v);
                        __nv_bfloat16 lo = __float2bfloat16(v - __bfloat162float(hi));
                        const uint32_t off = swz128((uint32_t)(rho*BCOLS + cc)*128 + (uint32_t)cil*2);
                        sts16(sbase + SMEM_B_HI + off, *(unsigned short*)&hi);
                        sts16(sbase + SMEM_B_LO + off, *(unsigned short*)&lo);
                    }
                }
            }
        }

        cp_waitall();          // this thread's A[s] parts landed
        __syncthreads();       // everyone's A[s] + B visible; prior compute finished

        if (s + 1 < NSTAGE) {  // prefetch A[s+1] into the other buffer
            const uint4* src = (const uint4*)(g_wpack + (size_t)(s+1)*32768);
            const uint32_t dst = sbase + (uint32_t)((s+1) & 1) * SMEM_ABUF;
            #pragma unroll
            for (int j = 0; j < 4; j++)
                cp_async16(dst + (uint32_t)(tid + j*CONV_THREADS)*16, src + tid + j*CONV_THREADS);
            cp_commit();
        }

        // ---- compute stage s ----
        const uint32_t a_hi = sbase + (uint32_t)(s & 1) * SMEM_ABUF;
        const int kh = tap / 3, kw = tap - kh*3;
        uint32_t boff[4], bxr[4];
        #pragma unroll
        for (int p = 0; p < 4; p++) {
            int pix = (hrow + kh)*BCOLS + colb + p*16 + (mtx >> 1)*8 + rowin + kw;
            boff[p] = (uint32_t)pix * 128;
            bxr[p]  = (uint32_t)(pix & 7) << 4;
        }

        #pragma unroll
        for (int ks = 0; ks < 4; ks++) {
            uint32_t ah[2][4], al[2][4];
            #pragma unroll
            for (int mt = 0; mt < 2; mt++) {
                const uint32_t ka = (uint32_t)ks*32 + kca;
                const uint32_t ad = a_hi + aoff[mt] + (ka ^ axr[mt]);
                ldsm4(ah[mt], ad);
                ldsm4(al[mt], ad + 16384);
            }
            #pragma unroll
            for (int p = 0; p < 4; p++) {
                uint32_t bh[4], bl[4];
                const uint32_t kb = (uint32_t)ks*32 + kcb;
                const uint32_t bd = sbase + SMEM_B_HI + boff[p] + (kb ^ bxr[p]);
                ldsm4(bh, bd);
                ldsm4(bl, bd + SMEM_B_SZ);
                #pragma unroll
                for (int mt = 0; mt < 2; mt++)
                    #pragma unroll
                    for (int q = 0; q < 2; q++) {
                        float* a4 = acc[mt][p*2 + q];
                        mma16816(a4, ah[mt], bh[q*2], bh[q*2+1]);  // hi*hi
                        mma16816(a4, al[mt], bh[q*2], bh[q*2+1]);  // lo(W)*hi(X)
                        mma16816(a4, ah[mt], bl[q*2], bl[q*2+1]);  // hi(W)*lo(X)
                    }
            }
        }
    }

    // ---- epilogue: bias + store + instance sums ----
    const int g  = lane >> 2;
    const int tg = lane & 3;
    const int row = r0 + hrow;
    #pragma unroll
    for (int mt = 0; mt < 2; mt++) {
        const int co0 = warp_m*32 + mt*16 + g;
        const int co1 = co0 + 8;
        const float b0 = __ldg(bias + co0);
        const float b1 = __ldg(bias + co1);
        float* yp0 = g_y + ((size_t)(n*CO + co0) * HH + row) * WW;
        float* yp1 = g_y + ((size_t)(n*CO + co1) * HH + row) * WW;
        float s0 = 0.f, q0 = 0.f, s1 = 0.f, q1 = 0.f;
        #pragma unroll
        for (int nt = 0; nt < 8; nt++) {
            const int pix = colb + nt*8 + 2*tg;
            float v0 = acc[mt][nt][0] + b0;
            float v1 = acc[mt][nt][1] + b0;
            float v2 = acc[mt][nt][2] + b1;
            float v3 = acc[mt][nt][3] + b1;
            float2 o0 = {v0, v1}, o1 = {v2, v3};
            *(float2*)(yp0 + pix) = o0;
            *(float2*)(yp1 + pix) = o1;
            s0 += v0 + v1;  q0 += v0*v0 + v1*v1;
            s1 += v2 + v3;  q1 += v2*v2 + v3*v3;
        }
        #pragma unroll
        for (int o = 1; o <= 2; o <<= 1) {
            s0 += __shfl_xor_sync(0xffffffffu, s0, o);
            q0 += __shfl_xor_sync(0xffffffffu, q0, o);
            s1 += __shfl_xor_sync(0xffffffffu, s1, o);
            q1 += __shfl_xor_sync(0xffffffffu, q1, o);
        }
        if (tg == 0) {
            atomicAdd(&g_sum[n*CO + co0], s0);
            atomicAdd(&g_sq [n*CO + co0], q0);
            atomicAdd(&g_sum[n*CO + co1], s1);
            atomicAdd(&g_sq [n*CO + co1], q1);
        }
    }
}

// ---------------- normalize + affine + ReLU ----------------
__global__ __launch_bounds__(256)
void norm_kernel(const float* __restrict__ gamma, const float* __restrict__ beta,
                 float* __restrict__ out)
{
    const int inst = blockIdx.x;
    const int c = inst & (CO - 1);
    const float mean = g_sum[inst] * (1.0f / HWSZ);
    const float var  = g_sq[inst] * (1.0f / HWSZ) - mean * mean;
    const float rstd = rsqrtf(var + EPS);
    const float sc = rstd * gamma[c];
    const float sh = beta[c] - mean * sc;

    const float4* yp = (const float4*)(g_y + (size_t)inst * HWSZ);
    float4* op = (float4*)(out + (size_t)inst * HWSZ);
    for (int i = threadIdx.x; i < HWSZ/4; i += 256) {
        float4 v = yp[i];
        float4 o;
        o.x = fmaxf(fmaf(v.x, sc, sh), 0.0f);
        o.y = fmaxf(fmaf(v.y, sc, sh), 0.0f);
        o.z = fmaxf(fmaf(v.z, sc, sh), 0.0f);
        o.w = fmaxf(fmaf(v.w, sc, sh), 0.0f);
        op[i] = o;
    }
}

extern "C" void kernel_launch(void* const* d_in, const int* in_sizes, int n_in,
                              void* d_out, int out_size)
{
    const float* x      = (const float*)d_in[0];
    const float* weight = (const float*)d_in[1];
    const float* bias   = (const float*)d_in[2];
    const float* gamma  = (const float*)d_in[3];
    const float* beta   = (const float*)d_in[4];
    float* out = (float*)d_out;

    cudaFuncSetAttribute(conv_mma_kernel, cudaFuncAttributeMaxDynamicSharedMemorySize, SMEM_TOTAL);

    prepack_kernel<<<(CO*CI*NTAP + 255)/256, 256>>>(weight);
    conv_mma_kernel<<<NN*(HH/ROWS_PER_CTA), CONV_THREADS, SMEM_TOTAL>>>(x, bias);
    norm_kernel<<<NN*CO, 256>>>(gamma, beta, out);
}